// round 3
// baseline (speedup 1.0000x reference)
#include <cuda_runtime.h>
#include <math.h>

#define TM 64
#define ND 128
#define NH 256
#define NMAX 40000
#define LN_EPS 1e-5f

// Scratch for scatter-mean aggregation (device globals: allocation-free).
__device__ float g_agg[(long long)NMAX * ND];
__device__ float g_cnt[NMAX];
__device__ int   g_is64;

// edge_index dtype auto-detect: if stored as int64 (little-endian, values < 2^31),
// every odd int32 word is the zero high-half. 100 consecutive zero odd words from
// random int32 indices in [0,40000) has probability ~ (1/40000)^100 ~= 0.
__global__ void detect_kernel(const int* __restrict__ p) {
    int all0 = 1;
    for (int i = 1; i < 200; i += 2)
        if (p[i] != 0) all0 = 0;
    g_is64 = all0;
}

__global__ void zero_kernel(int n) {
    long long i = (long long)blockIdx.x * blockDim.x + threadIdx.x;
    long long tot = (long long)n * ND;
    if (i < tot) g_agg[i] = 0.f;
    if (i < n)   g_cnt[i] = 0.f;
}

// MODE 0: edge MLP   (X = [sender_x[src] | receiver_x[dst] | edge_attr], K1=384)
// MODE 1: node MLP   (X = [receiver_x | agg/max(cnt,1)],                 K1=256)
// MODE 2: sender MLP (X = sender_x,                                      K1=128)
// Block: 64 rows, 256 threads. GEMM1 -> SiLU -> GEMM2 -> LayerNorm -> residual.
template<int MODE>
__global__ __launch_bounds__(256)
void mlp_kernel(const float* __restrict__ xa,
                const void*  __restrict__ eidx,
                const float* __restrict__ xb,      // receiver_x (edge mode)
                const float* __restrict__ xc,      // edge_attr  (edge mode)
                const float* __restrict__ w1, const float* __restrict__ b1,
                const float* __restrict__ w2, const float* __restrict__ b2,
                const float* __restrict__ gamma, const float* __restrict__ beta,
                const float* __restrict__ resid,
                float* __restrict__ outp,
                int nrows, int nedges)
{
    constexpr int K1 = (MODE == 0) ? 384 : (MODE == 1 ? 256 : 128);
    extern __shared__ float smem[];
    float* Xs   = smem;                  // [64][33]
    float* Ws   = smem + 2112;           // [32][256] (reused [32][128] in GEMM2)
    float* Hs   = smem + 2112 + 8192;    // [64][257]
    float* rcpv = smem + 26752;          // [64]
    int*   idxs = (int*)(smem + 26816);  // [64]
    int*   idxd = idxs + 64;             // [64]

    const int tid = threadIdx.x;
    const int tx  = tid & 15;
    const int ty  = tid >> 4;
    const long long row0 = (long long)blockIdx.x * TM;

    if (MODE == 0) {
        int is64 = g_is64;
        for (int i = tid; i < TM; i += 256) {
            long long e = row0 + i; if (e >= nrows) e = nrows - 1;
            if (is64) {
                const long long* p = (const long long*)eidx;
                idxs[i] = (int)p[e];
                idxd[i] = (int)p[(long long)nedges + e];
            } else {
                const int* p = (const int*)eidx;
                idxs[i] = p[e];
                idxd[i] = p[nedges + e];
            }
        }
    } else if (MODE == 1) {
        for (int i = tid; i < TM; i += 256) {
            long long r = row0 + i;
            float c = (r < nrows) ? g_cnt[r] : 1.f;
            rcpv[i] = 1.f / fmaxf(c, 1.f);
        }
    }
    __syncthreads();

    // ---------------- GEMM1: [64,K1] @ [K1,256] ----------------
    float acc[4][16];
    #pragma unroll
    for (int i = 0; i < 4; i++)
        #pragma unroll
        for (int j = 0; j < 16; j++) acc[i][j] = 0.f;

    for (int k0 = 0; k0 < K1; k0 += 32) {
        // stage X tile [64,32]
        #pragma unroll
        for (int it = 0; it < 8; it++) {
            int idx = tid + it * 256;          // 0..2047
            int r   = idx >> 5;
            int col = idx & 31;
            int k   = k0 + col;
            long long grow = row0 + r;
            if (grow >= nrows) grow = nrows - 1;
            float val;
            if (MODE == 0) {
                if (k < 128)      val = xa[(long long)idxs[r] * ND + k];
                else if (k < 256) val = xb[(long long)idxd[r] * ND + (k - 128)];
                else              val = xc[grow * ND + (k - 256)];
            } else if (MODE == 1) {
                if (k < 128) val = xa[grow * ND + k];
                else         val = g_agg[grow * ND + (k - 128)] * rcpv[r];
            } else {
                val = xa[grow * ND + k];
            }
            Xs[r * 33 + col] = val;
        }
        // stage W1 tile [32,256]
        {
            const float4* w1v = (const float4*)(w1 + (long long)k0 * NH);
            float4* Wv = (float4*)Ws;
            #pragma unroll
            for (int it = 0; it < 8; it++) {
                int v4 = tid + it * 256;       // 0..2047 float4
                Wv[v4] = w1v[v4];
            }
        }
        __syncthreads();
        #pragma unroll 4
        for (int kk = 0; kk < 32; kk++) {
            float xv[4];
            #pragma unroll
            for (int i = 0; i < 4; i++) xv[i] = Xs[(ty * 4 + i) * 33 + kk];
            const float4* wr = (const float4*)(Ws + kk * NH) + tx * 4;
            #pragma unroll
            for (int j4 = 0; j4 < 4; j4++) {
                float4 w = wr[j4];
                #pragma unroll
                for (int i = 0; i < 4; i++) {
                    acc[i][j4 * 4 + 0] += xv[i] * w.x;
                    acc[i][j4 * 4 + 1] += xv[i] * w.y;
                    acc[i][j4 * 4 + 2] += xv[i] * w.z;
                    acc[i][j4 * 4 + 3] += xv[i] * w.w;
                }
            }
        }
        __syncthreads();
    }

    // bias + SiLU -> Hs
    {
        float bb[16];
        #pragma unroll
        for (int j = 0; j < 16; j++) bb[j] = b1[tx * 16 + j];
        #pragma unroll
        for (int i = 0; i < 4; i++)
            #pragma unroll
            for (int j = 0; j < 16; j++) {
                float v = acc[i][j] + bb[j];
                Hs[(ty * 4 + i) * 257 + tx * 16 + j] = v / (1.f + expf(-v));
            }
    }
    __syncthreads();

    // ---------------- GEMM2: [64,256] @ [256,128] ----------------
    float acc2[4][8];
    #pragma unroll
    for (int i = 0; i < 4; i++)
        #pragma unroll
        for (int j = 0; j < 8; j++) acc2[i][j] = 0.f;

    for (int k0 = 0; k0 < NH; k0 += 32) {
        const float4* w2v = (const float4*)(w2 + (long long)k0 * ND);
        float4* Wv = (float4*)Ws;
        #pragma unroll
        for (int it = 0; it < 4; it++) {
            int v4 = tid + it * 256;           // 0..1023 float4
            Wv[v4] = w2v[v4];
        }
        __syncthreads();
        #pragma unroll 4
        for (int kk = 0; kk < 32; kk++) {
            float xv[4];
            #pragma unroll
            for (int i = 0; i < 4; i++) xv[i] = Hs[(ty * 4 + i) * 257 + k0 + kk];
            const float4* wr = (const float4*)(Ws + kk * ND) + tx * 2;
            float4 wa = wr[0], wb = wr[1];
            #pragma unroll
            for (int i = 0; i < 4; i++) {
                acc2[i][0] += xv[i] * wa.x; acc2[i][1] += xv[i] * wa.y;
                acc2[i][2] += xv[i] * wa.z; acc2[i][3] += xv[i] * wa.w;
                acc2[i][4] += xv[i] * wb.x; acc2[i][5] += xv[i] * wb.y;
                acc2[i][6] += xv[i] * wb.z; acc2[i][7] += xv[i] * wb.w;
            }
        }
        __syncthreads();
    }

    // ---------------- bias + LayerNorm + residual + (scatter) ----------------
    float bb2[8], gm[8], bt[8];
    #pragma unroll
    for (int j = 0; j < 8; j++) {
        int c = tx * 8 + j;
        bb2[j] = b2[c]; gm[j] = gamma[c]; bt[j] = beta[c];
    }
    #pragma unroll
    for (int i = 0; i < 4; i++) {
        float s = 0.f, q = 0.f;
        #pragma unroll
        for (int j = 0; j < 8; j++) {
            float v = acc2[i][j] + bb2[j];
            acc2[i][j] = v;
            s += v; q += v * v;
        }
        #pragma unroll
        for (int m = 1; m < 16; m <<= 1) {
            s += __shfl_xor_sync(0xffffffffu, s, m);
            q += __shfl_xor_sync(0xffffffffu, q, m);
        }
        float mean = s * (1.f / 128.f);
        float var  = q * (1.f / 128.f) - mean * mean;
        float inv  = rsqrtf(var + LN_EPS);
        long long grow = row0 + ty * 4 + i;
        if (grow < nrows) {
            float o[8];
            #pragma unroll
            for (int j = 0; j < 8; j++) o[j] = (acc2[i][j] - mean) * inv * gm[j] + bt[j];
            long long off = grow * ND + tx * 8;
            float4 r0 = *(const float4*)(resid + off);
            float4 r1 = *(const float4*)(resid + off + 4);
            float4 o0 = make_float4(o[0] + r0.x, o[1] + r0.y, o[2] + r0.z, o[3] + r0.w);
            float4 o1 = make_float4(o[4] + r1.x, o[5] + r1.y, o[6] + r1.z, o[7] + r1.w);
            *(float4*)(outp + off)     = o0;
            *(float4*)(outp + off + 4) = o1;
            if (MODE == 0) {
                int dd = idxd[ty * 4 + i];
                long long aoff = (long long)dd * ND + tx * 8;
                #pragma unroll
                for (int j = 0; j < 8; j++) atomicAdd(&g_agg[aoff + j], o[j]);
                if (tx == 0) atomicAdd(&g_cnt[dd], 1.f);
            }
        }
    }
}

extern "C" void kernel_launch(void* const* d_in, const int* in_sizes, int n_in,
                              void* d_out, int out_size)
{
    const float* sender_x   = (const float*)d_in[0];
    const float* receiver_x = (const float*)d_in[1];
    const float* edge_attr  = (const float*)d_in[2];
    const void*  eidx       = d_in[3];
    const float* ew1 = (const float*)d_in[4],  *eb1   = (const float*)d_in[5];
    const float* ew2 = (const float*)d_in[6],  *eb2   = (const float*)d_in[7];
    const float* eg  = (const float*)d_in[8],  *ebeta = (const float*)d_in[9];
    const float* nw1 = (const float*)d_in[10], *nb1   = (const float*)d_in[11];
    const float* nw2 = (const float*)d_in[12], *nb2   = (const float*)d_in[13];
    const float* ng  = (const float*)d_in[14], *nbeta = (const float*)d_in[15];
    const float* sw1 = (const float*)d_in[16], *sb1   = (const float*)d_in[17];
    const float* sw2 = (const float*)d_in[18], *sb2   = (const float*)d_in[19];
    const float* sg  = (const float*)d_in[20], *sbeta = (const float*)d_in[21];

    int N = in_sizes[0] / ND;
    int E = in_sizes[2] / ND;
    float* out = (float*)d_out;

    const int SMEM_BYTES = 107776;  // (2112 + 8192 + 16448 + 64 + 128) * 4
    cudaFuncSetAttribute(mlp_kernel<0>, cudaFuncAttributeMaxDynamicSharedMemorySize, SMEM_BYTES);
    cudaFuncSetAttribute(mlp_kernel<1>, cudaFuncAttributeMaxDynamicSharedMemorySize, SMEM_BYTES);
    cudaFuncSetAttribute(mlp_kernel<2>, cudaFuncAttributeMaxDynamicSharedMemorySize, SMEM_BYTES);

    detect_kernel<<<1, 1>>>((const int*)eidx);
    zero_kernel<<<(N * ND + 255) / 256, 256>>>(N);

    // edge MLP: writes edge_out (region 2) + scatters into g_agg/g_cnt
    mlp_kernel<0><<<(E + TM - 1) / TM, 256, SMEM_BYTES>>>(
        sender_x, eidx, receiver_x, edge_attr,
        ew1, eb1, ew2, eb2, eg, ebeta,
        edge_attr, out + 2LL * N * ND, E, E);

    // node MLP: reads g_agg/g_cnt, writes receiver_out (region 1)
    mlp_kernel<1><<<(N + TM - 1) / TM, 256, SMEM_BYTES>>>(
        receiver_x, nullptr, nullptr, nullptr,
        nw1, nb1, nw2, nb2, ng, nbeta,
        receiver_x, out + (long long)N * ND, N, 0);

    // sender MLP: writes sender_out (region 0)
    mlp_kernel<2><<<(N + TM - 1) / TM, 256, SMEM_BYTES>>>(
        sender_x, nullptr, nullptr, nullptr,
        sw1, sb1, sw2, sb2, sg, sbeta,
        sender_x, out, N, 0);
}

// round 6
// speedup vs baseline: 3.8244x; 3.8244x over previous
#include <cuda_runtime.h>
#include <cstdint>
#include <math.h>

#define ND 128
#define NMAX 40000
#define LN_EPS 1e-5f
#define TILE 128

// ---------------- device scratch (allocation-free) ----------------
__device__ float g_agg[(long long)NMAX * ND];
__device__ float g_cnt[NMAX];
__device__ int   g_is64;
__device__ float g_w1t[3][256 * 384];   // [N=256][K1] tf32-rounded, transposed W1
__device__ float g_w2t[3][128 * 256];   // [N=128][K=256] tf32-rounded, transposed W2

// ---------------- helpers ----------------
__device__ __forceinline__ float to_tf32(float x) {
    float r; asm("cvt.rna.tf32.f32 %0, %1;" : "=f"(r) : "f"(x)); return r;
}
__device__ __forceinline__ void red_add_v4(float* p, float4 v) {
    asm volatile("red.global.add.v4.f32 [%0], {%1,%2,%3,%4};"
                 :: "l"(p), "f"(v.x), "f"(v.y), "f"(v.z), "f"(v.w) : "memory");
}
// m16n8k8 tf32 mma: A row-major (4 regs), B col-major (2 regs), C/D f32 (4 regs)
__device__ __forceinline__ void mma8(float d[4], const uint32_t* a, const uint32_t* b) {
    asm volatile("mma.sync.aligned.m16n8k8.row.col.f32.tf32.tf32.f32 "
        "{%0,%1,%2,%3}, {%4,%5,%6,%7}, {%8,%9}, {%0,%1,%2,%3};"
        : "+f"(d[0]), "+f"(d[1]), "+f"(d[2]), "+f"(d[3])
        : "r"(a[0]), "r"(a[1]), "r"(a[2]), "r"(a[3]), "r"(b[0]), "r"(b[1]));
}

// ---------------- small kernels ----------------
__global__ void detect_kernel(const int* __restrict__ p) {
    int all0 = 1;
    for (int i = 1; i < 200; i += 2)
        if (p[i] != 0) all0 = 0;
    g_is64 = all0;
}
__global__ void zero_kernel(int n) {
    long long i = (long long)blockIdx.x * blockDim.x + threadIdx.x;
    long long tot = (long long)n * ND;
    if (i < tot) g_agg[i] = 0.f;
    if (i < n)   g_cnt[i] = 0.f;
}
// transpose + tf32-round: w1 [K1,256] -> g_w1t[S] [256,K1]; w2 [256,128] -> g_w2t[S] [128,256]
template<int S>
__global__ void prep_kernel(const float* __restrict__ w1, const float* __restrict__ w2, int K1) {
    int tot1 = K1 * 256;
    for (int i = blockIdx.x * blockDim.x + threadIdx.x; i < tot1; i += gridDim.x * blockDim.x) {
        int k = i >> 8, n = i & 255;
        g_w1t[S][n * K1 + k] = to_tf32(w1[i]);
    }
    int tot2 = 256 * 128;
    for (int i = blockIdx.x * blockDim.x + threadIdx.x; i < tot2; i += gridDim.x * blockDim.x) {
        int k = i >> 7, n = i & 127;
        g_w2t[S][n * 256 + k] = to_tf32(w2[i]);
    }
}

// ---------------- smem layout (floats) ----------------
// fragment-major packs:
//   apack[kb<4][mt<8][lane<32][4]  (X chunk, 4096 floats)
//   bpack[kb<4][nt  ][lane<32][2]  (W chunk, NT=32 gemm1 -> 8192 fl; NT=16 gemm2 -> 4096 fl)
//   hpack[kb2<32][mt<8][lane<32][4] (H full, 32768 floats) — overlaid by lnbuf[128][132]
#define OFF_IDXS  0
#define OFF_IDXD  128
#define OFF_RCP   256
#define OFF_MEAN  384
#define OFF_INV   512
#define OFF_APACK 640
#define OFF_BPACK (640 + 4096)
#define OFF_HPACK (640 + 12288)
#define SMEM_FLOATS (640 + 12288 + 32768)
#define SMEM_BYTES  (SMEM_FLOATS * 4)    // 182784

// MODE 0: edge (K1=384, gather + scatter), MODE 1: node (K1=256), MODE 2: sender (K1=128)
template<int MODE>
__global__ void __launch_bounds__(256, 1)
fused_mlp(const float* __restrict__ xa, const void* __restrict__ eidx,
          const float* __restrict__ xb, const float* __restrict__ xc,
          const float* __restrict__ b1, const float* __restrict__ b2,
          const float* __restrict__ gamma, const float* __restrict__ beta,
          const float* __restrict__ resid, float* __restrict__ outp,
          int nrows, int nedges)
{
    constexpr int K1  = (MODE == 0) ? 384 : (MODE == 1 ? 256 : 128);
    constexpr int NC1 = K1 / 32;
    extern __shared__ float sm[];
    int*   idxs  = (int*)(sm + OFF_IDXS);
    int*   idxd  = (int*)(sm + OFF_IDXD);
    float* rcp   = sm + OFF_RCP;
    float* smean = sm + OFF_MEAN;
    float* sinv  = sm + OFF_INV;
    float* apack = sm + OFF_APACK;
    float* bpack = sm + OFF_BPACK;
    float* hpack = sm + OFF_HPACK;
    float* lnbuf = sm + OFF_HPACK;   // overlay (used after GEMM2)

    const int tid  = threadIdx.x;
    const int lane = tid & 31;
    const int wid  = tid >> 5;
    const int wm   = wid & 1;        // warp m-block (0..1): rows wm*64..
    const int wn   = wid >> 1;       // warp n-block (0..3)
    const long long row0 = (long long)blockIdx.x * TILE;

    // -------- per-tile metadata --------
    if (MODE == 0) {
        if (tid < TILE) {
            int is64 = g_is64;
            long long e = row0 + tid; if (e >= nrows) e = nrows - 1;
            if (is64) {
                const long long* p = (const long long*)eidx;
                idxs[tid] = (int)p[e];
                idxd[tid] = (int)p[(long long)nedges + e];
            } else {
                const int* p = (const int*)eidx;
                idxs[tid] = p[e];
                idxd[tid] = p[nedges + e];
            }
        }
    } else if (MODE == 1) {
        if (tid < TILE) {
            long long r = row0 + tid;
            float c = (r < nrows) ? g_cnt[r] : 1.f;
            rcp[tid] = 1.f / fmaxf(c, 1.f);
        }
    }
    __syncthreads();

    const float* w1t = g_w1t[MODE];
    const float* w2t = g_w2t[MODE];

    // ================= GEMM1: D1[128,256] = X[128,K1] @ W1 =================
    float d1[4][8][4];
    #pragma unroll
    for (int i = 0; i < 4; i++)
        #pragma unroll
        for (int j = 0; j < 8; j++)
            #pragma unroll
            for (int c = 0; c < 4; c++) d1[i][j][c] = 0.f;

    for (int c = 0; c < NC1; c++) {
        __syncthreads();   // previous mma done before restage
        // ---- stage X chunk [128 rows][32 k] into apack (fragment-major) ----
        #pragma unroll
        for (int t = 0; t < 4; t++) {
            int idx = tid + t * 256;            // 0..1023: row(128) x kq(8 float4s)
            int row = idx >> 3, kq = idx & 7;
            long long grow = row0 + row; if (grow >= nrows) grow = nrows - 1;
            int kglob = c * 32 + kq * 4;
            const float* src;
            float scale = 1.f;
            if (MODE == 0) {
                src = (kglob < 128) ? xa + (long long)idxs[row] * ND + kglob
                    : (kglob < 256) ? xb + (long long)idxd[row] * ND + (kglob - 128)
                                    : xc + grow * ND + (kglob - 256);
            } else if (MODE == 1) {
                if (kglob < 128) src = xa + grow * ND + kglob;
                else { src = g_agg + grow * ND + (kglob - 128); scale = rcp[row]; }
            } else {
                src = xa + grow * ND + kglob;
            }
            float4 v = *(const float4*)src;
            v.x = to_tf32(v.x * scale); v.y = to_tf32(v.y * scale);
            v.z = to_tf32(v.z * scale); v.w = to_tf32(v.w * scale);
            int kb = kq >> 1, mt = row >> 4, lr = row & 15;
            int r  = (lr >> 3) + 2 * (kq & 1);
            float* dst = apack + (((kb * 8 + mt) * 32 + (lr & 7) * 4) << 2) + r;
            dst[0] = v.x; dst[4] = v.y; dst[8] = v.z; dst[12] = v.w;
        }
        // ---- stage W1T chunk [256 n][32 k] into bpack ----
        #pragma unroll
        for (int t = 0; t < 8; t++) {
            int idx = tid + t * 256;            // 0..2047: n(256) x kq(8)
            int n = idx >> 3, kq = idx & 7;
            float4 v = *(const float4*)(w1t + (long long)n * K1 + c * 32 + kq * 4);
            int kb = kq >> 1, r = kq & 1, nt = n >> 3;
            float* dst = bpack + (((kb * 32 + nt) * 32 + (n & 7) * 4) << 1) + r;
            dst[0] = v.x; dst[2] = v.y; dst[4] = v.z; dst[6] = v.w;
        }
        __syncthreads();
        // ---- mma: 4 k8 blocks ----
        #pragma unroll
        for (int kb = 0; kb < 4; kb++) {
            uint4 a[4]; uint2 b[8];
            #pragma unroll
            for (int i = 0; i < 4; i++)
                a[i] = *(const uint4*)(apack + (((kb * 8 + wm * 4 + i) * 32 + lane) << 2));
            #pragma unroll
            for (int j = 0; j < 8; j++)
                b[j] = *(const uint2*)(bpack + (((kb * 32 + wn * 8 + j) * 32 + lane) << 1));
            #pragma unroll
            for (int i = 0; i < 4; i++)
                #pragma unroll
                for (int j = 0; j < 8; j++)
                    mma8(d1[i][j], (const uint32_t*)&a[i], (const uint32_t*)&b[j]);
        }
    }
    __syncthreads();

    // ======== epilogue1: bias + SiLU -> hpack (GEMM2 A-fragment layout) ========
    #pragma unroll
    for (int j = 0; j < 8; j++) {
        int nbase = wn * 64 + j * 8 + (lane & 3) * 2;
        float bv0 = b1[nbase], bv1 = b1[nbase + 1];
        #pragma unroll
        for (int i = 0; i < 4; i++) {
            #pragma unroll
            for (int cc = 0; cc < 4; cc++) {
                float v = d1[i][j][cc] + ((cc & 1) ? bv1 : bv0);
                v = to_tf32(v / (1.f + __expf(-v)));
                int x     = (lane & 3) * 2 + (cc & 1);
                int lanep = (lane >> 2) * 4 + (x & 3);
                int rp    = (cc >> 1) + ((x >> 2) << 1);
                int kb2   = wn * 8 + j;
                int mt    = wm * 4 + i;
                hpack[(((kb2 * 8 + mt) * 32 + lanep) << 2) + rp] = v;
            }
        }
    }
    __syncthreads();

    // ================= GEMM2: D2[128,128] = H[128,256] @ W2 =================
    float d2[4][4][4];
    #pragma unroll
    for (int i = 0; i < 4; i++)
        #pragma unroll
        for (int j = 0; j < 4; j++)
            #pragma unroll
            for (int c = 0; c < 4; c++) d2[i][j][c] = 0.f;

    for (int c2 = 0; c2 < 8; c2++) {
        __syncthreads();
        // stage W2T chunk [128 n][32 k] into bpack (NT=16)
        #pragma unroll
        for (int t = 0; t < 4; t++) {
            int idx = tid + t * 256;            // 0..1023
            int n = idx >> 3, kq = idx & 7;
            float4 v = *(const float4*)(w2t + (long long)n * 256 + c2 * 32 + kq * 4);
            int kb = kq >> 1, r = kq & 1, nt = n >> 3;
            float* dst = bpack + (((kb * 16 + nt) * 32 + (n & 7) * 4) << 1) + r;
            dst[0] = v.x; dst[2] = v.y; dst[4] = v.z; dst[6] = v.w;
        }
        __syncthreads();
        #pragma unroll
        for (int kb = 0; kb < 4; kb++) {
            int kb2 = c2 * 4 + kb;
            uint4 a[4]; uint2 b[4];
            #pragma unroll
            for (int i = 0; i < 4; i++)
                a[i] = *(const uint4*)(hpack + (((kb2 * 8 + wm * 4 + i) * 32 + lane) << 2));
            #pragma unroll
            for (int j = 0; j < 4; j++)
                b[j] = *(const uint2*)(bpack + (((kb * 16 + wn * 4 + j) * 32 + lane) << 1));
            #pragma unroll
            for (int i = 0; i < 4; i++)
                #pragma unroll
                for (int j = 0; j < 4; j++)
                    mma8(d2[i][j], (const uint32_t*)&a[i], (const uint32_t*)&b[j]);
        }
    }
    __syncthreads();   // hpack reads done; lnbuf overlay safe

    // ======== epilogue2: bias -> lnbuf, LN stats, LN+residual+store+scatter ========
    #pragma unroll
    for (int j = 0; j < 4; j++) {
        int nbase = wn * 32 + j * 8 + (lane & 3) * 2;
        float bv0 = b2[nbase], bv1 = b2[nbase + 1];
        #pragma unroll
        for (int i = 0; i < 4; i++) {
            int mbase = wm * 64 + i * 16 + (lane >> 2);
            #pragma unroll
            for (int cc = 0; cc < 4; cc++) {
                int m = mbase + (cc >> 1) * 8;
                int n = nbase + (cc & 1);
                lnbuf[m * 132 + n] = d2[i][j][cc] + ((cc & 1) ? bv1 : bv0);
            }
        }
    }
    __syncthreads();
    {   // per-row mean/inv-std: 2 threads per row
        int row = tid >> 1, h = tid & 1;
        const float* p = lnbuf + row * 132 + h * 64;
        float s = 0.f, q = 0.f;
        #pragma unroll
        for (int k = 0; k < 64; k++) { float v = p[k]; s += v; q += v * v; }
        s += __shfl_xor_sync(0xffffffffu, s, 1);
        q += __shfl_xor_sync(0xffffffffu, q, 1);
        float mean = s * (1.f / 128.f);
        float var  = q * (1.f / 128.f) - mean * mean;
        smean[row] = mean;
        sinv[row]  = rsqrtf(var + LN_EPS);
    }
    __syncthreads();
    #pragma unroll
    for (int t = 0; t < 16; t++) {
        int idx = tid + t * 256;               // 0..4095: row(128) x f(32 float4)
        int r2 = idx >> 5, f = idx & 31;
        long long grow = row0 + r2;
        if (grow < nrows) {
            float4 vv = *(const float4*)(lnbuf + r2 * 132 + f * 4);
            float mean = smean[r2], inv = sinv[r2];
            float4 gm = ((const float4*)gamma)[f];
            float4 bt = ((const float4*)beta)[f];
            float4 ln;
            ln.x = (vv.x - mean) * inv * gm.x + bt.x;
            ln.y = (vv.y - mean) * inv * gm.y + bt.y;
            ln.z = (vv.z - mean) * inv * gm.z + bt.z;
            ln.w = (vv.w - mean) * inv * gm.w + bt.w;
            float4 rs = ((const float4*)(resid + grow * ND))[f];
            float4 o = make_float4(ln.x + rs.x, ln.y + rs.y, ln.z + rs.z, ln.w + rs.w);
            ((float4*)(outp + grow * ND))[f] = o;
            if (MODE == 0)
                red_add_v4(g_agg + (long long)idxd[r2] * ND + f * 4, ln);
        }
    }
    if (MODE == 0 && tid < TILE) {
        long long grow = row0 + tid;
        if (grow < nrows) atomicAdd(&g_cnt[idxd[tid]], 1.f);
    }
}

// ---------------- host launch ----------------
extern "C" void kernel_launch(void* const* d_in, const int* in_sizes, int n_in,
                              void* d_out, int out_size)
{
    const float* sender_x   = (const float*)d_in[0];
    const float* receiver_x = (const float*)d_in[1];
    const float* edge_attr  = (const float*)d_in[2];
    const void*  eidx       = d_in[3];
    const float* ew1 = (const float*)d_in[4],  *eb1   = (const float*)d_in[5];
    const float* ew2 = (const float*)d_in[6],  *eb2   = (const float*)d_in[7];
    const float* eg  = (const float*)d_in[8],  *ebeta = (const float*)d_in[9];
    const float* nw1 = (const float*)d_in[10], *nb1   = (const float*)d_in[11];
    const float* nw2 = (const float*)d_in[12], *nb2   = (const float*)d_in[13];
    const float* ng  = (const float*)d_in[14], *nbeta = (const float*)d_in[15];
    const float* sw1 = (const float*)d_in[16], *sb1   = (const float*)d_in[17];
    const float* sw2 = (const float*)d_in[18], *sb2   = (const float*)d_in[19];
    const float* sg  = (const float*)d_in[20], *sbeta = (const float*)d_in[21];

    int N = in_sizes[0] / ND;
    int E = in_sizes[2] / ND;
    float* out = (float*)d_out;

    cudaFuncSetAttribute(fused_mlp<0>, cudaFuncAttributeMaxDynamicSharedMemorySize, SMEM_BYTES);
    cudaFuncSetAttribute(fused_mlp<1>, cudaFuncAttributeMaxDynamicSharedMemorySize, SMEM_BYTES);
    cudaFuncSetAttribute(fused_mlp<2>, cudaFuncAttributeMaxDynamicSharedMemorySize, SMEM_BYTES);

    detect_kernel<<<1, 1>>>((const int*)eidx);
    zero_kernel<<<(N * ND + 255) / 256, 256>>>(N);
    prep_kernel<0><<<512, 256>>>(ew1, ew2, 384);
    prep_kernel<1><<<512, 256>>>(nw1, nw2, 256);
    prep_kernel<2><<<512, 256>>>(sw1, sw2, 128);

    // edge: writes edge_out (region 2) + scatters into g_agg/g_cnt
    fused_mlp<0><<<(E + TILE - 1) / TILE, 256, SMEM_BYTES>>>(
        sender_x, eidx, receiver_x, edge_attr,
        eb1, eb2, eg, ebeta,
        edge_attr, out + 2LL * N * ND, E, E);

    // node: reads g_agg/g_cnt, writes receiver_out (region 1)
    fused_mlp<1><<<(N + TILE - 1) / TILE, 256, SMEM_BYTES>>>(
        receiver_x, nullptr, nullptr, nullptr,
        nb1, nb2, ng, nbeta,
        receiver_x, out + (long long)N * ND, N, 0);

    // sender: writes sender_out (region 0)
    fused_mlp<2><<<(N + TILE - 1) / TILE, 256, SMEM_BYTES>>>(
        sender_x, nullptr, nullptr, nullptr,
        sb1, sb2, sg, sbeta,
        sender_x, out, N, 0);
}

// round 7
// speedup vs baseline: 6.6176x; 1.7304x over previous
#include <cuda_runtime.h>
#include <cstdint>
#include <math.h>

#define ND 128
#define NMAX 40000
#define LN_EPS 1e-5f
#define TILE 128

// ---------------- device scratch (allocation-free) ----------------
__device__ float g_agg[(long long)NMAX * ND];
__device__ float g_cnt[NMAX];
__device__ int   g_is64;
// weights pre-rounded to tf32 AND pre-packed into the mma B-fragment chunk layout:
// g_w1p[mode]: per k-chunk c (32 k): 8192 floats = ((kb*32+nt)*32+lane)*2+r
// g_w2p[mode]: per k-chunk c:        4096 floats = ((kb*16+nt)*32+lane)*2+r
__device__ float g_w1p[3][384 * 256];
__device__ float g_w2p[3][256 * 128];

// ---------------- helpers ----------------
__device__ __forceinline__ float to_tf32(float x) {
    float r; asm("cvt.rna.tf32.f32 %0, %1;" : "=f"(r) : "f"(x)); return r;
}
__device__ __forceinline__ uint32_t smem_u32(const void* p) {
    uint32_t a;
    asm("{ .reg .u64 t; cvta.to.shared.u64 t, %1; cvt.u32.u64 %0, t; }" : "=r"(a) : "l"(p));
    return a;
}
__device__ __forceinline__ void red_add_v4(float* p, float4 v) {
    asm volatile("red.global.add.v4.f32 [%0], {%1,%2,%3,%4};"
                 :: "l"(p), "f"(v.x), "f"(v.y), "f"(v.z), "f"(v.w) : "memory");
}
// m16n8k8 tf32 mma: A row-major (4 regs), B col-major (2 regs), C/D f32 (4 regs)
__device__ __forceinline__ void mma8(float d[4], const uint32_t* a, const uint32_t* b) {
    asm volatile("mma.sync.aligned.m16n8k8.row.col.f32.tf32.tf32.f32 "
        "{%0,%1,%2,%3}, {%4,%5,%6,%7}, {%8,%9}, {%0,%1,%2,%3};"
        : "+f"(d[0]), "+f"(d[1]), "+f"(d[2]), "+f"(d[3])
        : "r"(a[0]), "r"(a[1]), "r"(a[2]), "r"(a[3]), "r"(b[0]), "r"(b[1]));
}
__device__ __forceinline__ void cpa16(uint32_t dst, const void* src) {
    asm volatile("cp.async.cg.shared.global [%0], [%1], 16;" :: "r"(dst), "l"(src) : "memory");
}
#define CP_COMMIT() asm volatile("cp.async.commit_group;" ::: "memory")
#define CP_WAIT0()  asm volatile("cp.async.wait_group 0;" ::: "memory")
#define CP_WAIT1()  asm volatile("cp.async.wait_group 1;" ::: "memory")

// ---------------- small kernels ----------------
__global__ void detect_kernel(const int* __restrict__ p) {
    int all0 = 1;
    for (int i = 1; i < 200; i += 2)
        if (p[i] != 0) all0 = 0;
    g_is64 = all0;
}
__global__ void zero_kernel(int n) {
    long long i = (long long)blockIdx.x * blockDim.x + threadIdx.x;
    long long tot = (long long)n * ND;
    if (i < tot) g_agg[i] = 0.f;
    if (i < n)   g_cnt[i] = 0.f;
}
// round + pack weights into fragment-chunk layout
template<int S>
__global__ void prep_kernel(const float* __restrict__ w1, const float* __restrict__ w2, int K1) {
    int tot1 = K1 * 256;
    for (int i = blockIdx.x * blockDim.x + threadIdx.x; i < tot1; i += gridDim.x * blockDim.x) {
        int k = i >> 8, n = i & 255;
        float v = to_tf32(w1[i]);
        int c = k >> 5, kq = (k & 31) >> 2, e = k & 3;
        int kb = kq >> 1, r = kq & 1;
        g_w1p[S][c * 8192 + (((kb * 32 + (n >> 3)) * 32 + (n & 7) * 4 + e) << 1) + r] = v;
    }
    int tot2 = 256 * 128;
    for (int i = blockIdx.x * blockDim.x + threadIdx.x; i < tot2; i += gridDim.x * blockDim.x) {
        int k = i >> 7, n = i & 127;
        float v = to_tf32(w2[i]);
        int c = k >> 5, kq = (k & 31) >> 2, e = k & 3;
        int kb = kq >> 1, r = kq & 1;
        g_w2p[S][c * 4096 + (((kb * 16 + (n >> 3)) * 32 + (n & 7) * 4 + e) << 1) + r] = v;
    }
}

// ---------------- smem layout (floats) ----------------
//   [0..128)   idxs   [128..256) idxd   [256..384) rcp  [384..512) smean [512..640) sinv
//   [640..8832)    bpack2: 2 x 4096   (GEMM2 W chunks)
//   [8832..41600)  hpack: 32768       (GEMM2 A / lnbuf overlay)
//     overlay during GEMM1: xraw 2 x (128x36) @8832 ; bpack1 2 x 8192 @18048
#define SMEM_FLOATS 41600
#define SMEM_BYTES  (SMEM_FLOATS * 4)   // 166400

// MODE 0: edge (K1=384, gather + scatter), MODE 1: node (K1=256), MODE 2: sender (K1=128)
template<int MODE>
__device__ __forceinline__ void mlp_body(
    int bid, float* sm, uint32_t sbase,
    const float* __restrict__ xa, const void* __restrict__ eidx,
    const float* __restrict__ xb, const float* __restrict__ xc,
    const float* __restrict__ b1, const float* __restrict__ b2,
    const float* __restrict__ gamma, const float* __restrict__ beta,
    const float* __restrict__ resid, float* __restrict__ outp,
    int nrows, int nedges)
{
    constexpr int K1  = (MODE == 0) ? 384 : (MODE == 1 ? 256 : 128);
    constexpr int NC1 = K1 / 32;
    int*   idxs  = (int*)sm;
    int*   idxd  = (int*)(sm + 128);
    float* rcp   = sm + 256;
    float* smean = sm + 384;
    float* sinv  = sm + 512;
    float* bpack2 = sm + 640;
    float* hpack  = sm + 8832;
    float* lnbuf  = hpack;
    float* xraw   = sm + 8832;
    float* bpack1 = sm + 18048;
    const uint32_t xr_b  = sbase + 8832u * 4u;
    const uint32_t bp1_b = sbase + 18048u * 4u;
    const uint32_t bp2_b = sbase + 640u * 4u;

    const int tid  = threadIdx.x;
    const int lane = tid & 31;
    const int wid  = tid >> 5;
    const int wm   = wid & 1;        // warp m-block (rows wm*64..)
    const int wn   = wid >> 1;       // warp n-block
    const long long row0 = (long long)bid * TILE;

    // -------- per-tile metadata --------
    if (MODE == 0) {
        if (tid < TILE) {
            int is64 = g_is64;
            long long e = row0 + tid; if (e >= nrows) e = nrows - 1;
            if (is64) {
                const long long* p = (const long long*)eidx;
                idxs[tid] = (int)p[e];
                idxd[tid] = (int)p[(long long)nedges + e];
            } else {
                const int* p = (const int*)eidx;
                idxs[tid] = p[e];
                idxd[tid] = p[nedges + e];
            }
        }
    } else if (MODE == 1) {
        if (tid < TILE) {
            long long r = row0 + tid;
            float c = (r < nrows) ? g_cnt[r] : 1.f;
            rcp[tid] = 1.f / fmaxf(c, 1.f);
        }
    }
    __syncthreads();

    const float* w1p = g_w1p[MODE];
    const float* w2p = g_w2p[MODE];

    // issue one GEMM1 chunk (X raw rows + W1 fragment-pack), one commit group
    auto issue1 = [&](int c) {
        int buf = c & 1;
        #pragma unroll
        for (int t = 0; t < 4; t++) {
            int seg = tid + t * 256;          // 0..1023 (128 rows x 8 16B-segs)
            int row = seg >> 3, f = seg & 7;
            long long grow = row0 + row; if (grow >= nrows) grow = nrows - 1;
            const float* src;
            if (MODE == 0) {
                src = (c < 4) ? xa + (long long)idxs[row] * ND + c * 32 + f * 4
                    : (c < 8) ? xb + (long long)idxd[row] * ND + (c - 4) * 32 + f * 4
                              : xc + grow * ND + (c - 8) * 32 + f * 4;
            } else if (MODE == 1) {
                src = (c < 4) ? xa + grow * ND + c * 32 + f * 4
                              : g_agg + grow * ND + (c - 4) * 32 + f * 4;
            } else {
                src = xa + grow * ND + c * 32 + f * 4;
            }
            cpa16(xr_b + (uint32_t)(buf * 4608 + row * 36 + f * 4) * 4u, src);
        }
        #pragma unroll
        for (int t = 0; t < 8; t++) {
            int seg = tid + t * 256;          // 0..2047 16B-segs
            cpa16(bp1_b + (uint32_t)(buf * 8192 + seg * 4) * 4u,
                  w1p + (long long)c * 8192 + seg * 4);
        }
        CP_COMMIT();
    };

    issue1(0);
    issue1(1);

    // ================= GEMM1: D1[128,256] = X[128,K1] @ W1 =================
    float d1[4][8][4];
    #pragma unroll
    for (int i = 0; i < 4; i++)
        #pragma unroll
        for (int j = 0; j < 8; j++)
            #pragma unroll
            for (int c = 0; c < 4; c++) d1[i][j][c] = 0.f;

    for (int c = 0; c < NC1; c++) {
        if (c == NC1 - 1) { CP_WAIT0(); } else { CP_WAIT1(); }
        __syncthreads();
        const float* xb_ = xraw + (c & 1) * 4608;
        const float* wb_ = bpack1 + (c & 1) * 8192;
        float rc1[4], rc2[4];
        if (MODE == 1 && c >= 4) {
            #pragma unroll
            for (int i = 0; i < 4; i++) {
                int row = wm * 64 + i * 16 + (lane >> 2);
                rc1[i] = rcp[row]; rc2[i] = rcp[row + 8];
            }
        }
        #pragma unroll
        for (int kb = 0; kb < 4; kb++) {
            uint2 b[8];
            #pragma unroll
            for (int j = 0; j < 8; j++)
                b[j] = *(const uint2*)(wb_ + (((kb * 32 + wn * 8 + j) * 32 + lane) << 1));
            #pragma unroll
            for (int i = 0; i < 4; i++) {
                int row = wm * 64 + i * 16 + (lane >> 2);
                const float* ap = xb_ + row * 36 + kb * 8 + (lane & 3);
                float a0 = ap[0], a1 = ap[288], a2 = ap[4], a3 = ap[292];
                if (MODE == 1 && c >= 4) { a0 *= rc1[i]; a2 *= rc1[i]; a1 *= rc2[i]; a3 *= rc2[i]; }
                uint32_t ar[4];
                ar[0] = __float_as_uint(to_tf32(a0));
                ar[1] = __float_as_uint(to_tf32(a1));
                ar[2] = __float_as_uint(to_tf32(a2));
                ar[3] = __float_as_uint(to_tf32(a3));
                #pragma unroll
                for (int j = 0; j < 8; j++)
                    mma8(d1[i][j], ar, (const uint32_t*)&b[j]);
            }
        }
        __syncthreads();
        if (c + 2 < NC1) issue1(c + 2);
    }

    // prefetch GEMM2 W chunks 0,1 (bpack2 is disjoint from hpack)
    auto issue2 = [&](int c2) {
        int buf = c2 & 1;
        #pragma unroll
        for (int t = 0; t < 4; t++) {
            int seg = tid + t * 256;          // 0..1023 16B-segs
            cpa16(bp2_b + (uint32_t)(buf * 4096 + seg * 4) * 4u,
                  w2p + (long long)c2 * 4096 + seg * 4);
        }
        CP_COMMIT();
    };
    issue2(0);
    issue2(1);

    // ======== epilogue1: bias + SiLU -> hpack (GEMM2 A-fragment layout) ========
    #pragma unroll
    for (int j = 0; j < 8; j++) {
        int nbase = wn * 64 + j * 8 + (lane & 3) * 2;
        float bv0 = b1[nbase], bv1 = b1[nbase + 1];
        #pragma unroll
        for (int i = 0; i < 4; i++) {
            #pragma unroll
            for (int cc = 0; cc < 4; cc++) {
                float v = d1[i][j][cc] + ((cc & 1) ? bv1 : bv0);
                v = to_tf32(v / (1.f + __expf(-v)));
                int x     = (lane & 3) * 2 + (cc & 1);
                int lanep = (lane >> 2) * 4 + (x & 3);
                int rp    = (cc >> 1) + ((x >> 2) << 1);
                int kb2   = wn * 8 + j;
                int mt    = wm * 4 + i;
                hpack[(((kb2 * 8 + mt) * 32 + lanep) << 2) + rp] = v;
            }
        }
    }
    __syncthreads();

    // ================= GEMM2: D2[128,128] = H[128,256] @ W2 =================
    float d2[4][4][4];
    #pragma unroll
    for (int i = 0; i < 4; i++)
        #pragma unroll
        for (int j = 0; j < 4; j++)
            #pragma unroll
            for (int c = 0; c < 4; c++) d2[i][j][c] = 0.f;

    for (int c2 = 0; c2 < 8; c2++) {
        if (c2 == 7) { CP_WAIT0(); } else { CP_WAIT1(); }
        __syncthreads();
        const float* wb_ = bpack2 + (c2 & 1) * 4096;
        #pragma unroll
        for (int kb = 0; kb < 4; kb++) {
            int kb2 = c2 * 4 + kb;
            uint4 a[4]; uint2 b[4];
            #pragma unroll
            for (int i = 0; i < 4; i++)
                a[i] = *(const uint4*)(hpack + (((kb2 * 8 + wm * 4 + i) * 32 + lane) << 2));
            #pragma unroll
            for (int j = 0; j < 4; j++)
                b[j] = *(const uint2*)(wb_ + (((kb * 16 + wn * 4 + j) * 32 + lane) << 1));
            #pragma unroll
            for (int i = 0; i < 4; i++)
                #pragma unroll
                for (int j = 0; j < 4; j++)
                    mma8(d2[i][j], (const uint32_t*)&a[i], (const uint32_t*)&b[j]);
        }
        __syncthreads();
        if (c2 + 2 < 8) issue2(c2 + 2);
    }

    // ======== epilogue2: bias -> lnbuf, LN stats, LN+residual+store+scatter ========
    #pragma unroll
    for (int j = 0; j < 4; j++) {
        int nbase = wn * 32 + j * 8 + (lane & 3) * 2;
        float bv0 = b2[nbase], bv1 = b2[nbase + 1];
        #pragma unroll
        for (int i = 0; i < 4; i++) {
            int mbase = wm * 64 + i * 16 + (lane >> 2);
            #pragma unroll
            for (int cc = 0; cc < 4; cc++) {
                int m = mbase + (cc >> 1) * 8;
                int n = nbase + (cc & 1);
                lnbuf[m * 132 + n] = d2[i][j][cc] + ((cc & 1) ? bv1 : bv0);
            }
        }
    }
    __syncthreads();
    {   // per-row mean/inv-std: 2 threads per row
        int row = tid >> 1, h = tid & 1;
        const float* p = lnbuf + row * 132 + h * 64;
        float s = 0.f, q = 0.f;
        #pragma unroll
        for (int k = 0; k < 64; k++) { float v = p[k]; s += v; q += v * v; }
        s += __shfl_xor_sync(0xffffffffu, s, 1);
        q += __shfl_xor_sync(0xffffffffu, q, 1);
        float mean = s * (1.f / 128.f);
        float var  = q * (1.f / 128.f) - mean * mean;
        smean[row] = mean;
        sinv[row]  = rsqrtf(var + LN_EPS);
    }
    __syncthreads();
    #pragma unroll
    for (int t = 0; t < 16; t++) {
        int idx = tid + t * 256;               // 0..4095: row(128) x f(32 float4)
        int r2 = idx >> 5, f = idx & 31;
        long long grow = row0 + r2;
        if (grow < nrows) {
            float4 vv = *(const float4*)(lnbuf + r2 * 132 + f * 4);
            float mean = smean[r2], inv = sinv[r2];
            float4 gm = ((const float4*)gamma)[f];
            float4 bt = ((const float4*)beta)[f];
            float4 ln;
            ln.x = (vv.x - mean) * inv * gm.x + bt.x;
            ln.y = (vv.y - mean) * inv * gm.y + bt.y;
            ln.z = (vv.z - mean) * inv * gm.z + bt.z;
            ln.w = (vv.w - mean) * inv * gm.w + bt.w;
            float4 rs = ((const float4*)(resid + grow * ND))[f];
            float4 o = make_float4(ln.x + rs.x, ln.y + rs.y, ln.z + rs.z, ln.w + rs.w);
            ((float4*)(outp + grow * ND))[f] = o;
            if (MODE == 0)
                red_add_v4(g_agg + (long long)idxd[r2] * ND + f * 4, ln);
        }
    }
    if (MODE == 0 && tid < TILE) {
        long long grow = row0 + tid;
        if (grow < nrows) atomicAdd(&g_cnt[idxd[tid]], 1.f);
    }
}

// ---------------- kernels ----------------
__global__ void __launch_bounds__(256, 1)
fused_edge_sender(const float* __restrict__ sender_x, const void* __restrict__ eidx,
                  const float* __restrict__ receiver_x, const float* __restrict__ edge_attr,
                  const float* __restrict__ eb1, const float* __restrict__ eb2,
                  const float* __restrict__ eg, const float* __restrict__ ebeta,
                  const float* __restrict__ sb1, const float* __restrict__ sb2,
                  const float* __restrict__ sg, const float* __restrict__ sbeta,
                  float* edge_out, float* sender_out, int E, int N, int nEdgeBlk)
{
    extern __shared__ float sm[];
    uint32_t sbase = smem_u32(sm);
    if ((int)blockIdx.x < nEdgeBlk)
        mlp_body<0>(blockIdx.x, sm, sbase, sender_x, eidx, receiver_x, edge_attr,
                    eb1, eb2, eg, ebeta, edge_attr, edge_out, E, E);
    else
        mlp_body<2>(blockIdx.x - nEdgeBlk, sm, sbase, sender_x, nullptr, nullptr, nullptr,
                    sb1, sb2, sg, sbeta, sender_x, sender_out, N, 0);
}

__global__ void __launch_bounds__(256, 1)
fused_node(const float* __restrict__ receiver_x,
           const float* __restrict__ nb1, const float* __restrict__ nb2,
           const float* __restrict__ ng, const float* __restrict__ nbeta,
           float* recv_out, int N)
{
    extern __shared__ float sm[];
    uint32_t sbase = smem_u32(sm);
    mlp_body<1>(blockIdx.x, sm, sbase, receiver_x, nullptr, nullptr, nullptr,
                nb1, nb2, ng, nbeta, receiver_x, recv_out, N, 0);
}

// ---------------- host launch ----------------
extern "C" void kernel_launch(void* const* d_in, const int* in_sizes, int n_in,
                              void* d_out, int out_size)
{
    const float* sender_x   = (const float*)d_in[0];
    const float* receiver_x = (const float*)d_in[1];
    const float* edge_attr  = (const float*)d_in[2];
    const void*  eidx       = d_in[3];
    const float* ew1 = (const float*)d_in[4],  *eb1   = (const float*)d_in[5];
    const float* ew2 = (const float*)d_in[6],  *eb2   = (const float*)d_in[7];
    const float* eg  = (const float*)d_in[8],  *ebeta = (const float*)d_in[9];
    const float* nw1 = (const float*)d_in[10], *nb1   = (const float*)d_in[11];
    const float* nw2 = (const float*)d_in[12], *nb2   = (const float*)d_in[13];
    const float* ng  = (const float*)d_in[14], *nbeta = (const float*)d_in[15];
    const float* sw1 = (const float*)d_in[16], *sb1   = (const float*)d_in[17];
    const float* sw2 = (const float*)d_in[18], *sb2   = (const float*)d_in[19];
    const float* sg  = (const float*)d_in[20], *sbeta = (const float*)d_in[21];

    int N = in_sizes[0] / ND;
    int E = in_sizes[2] / ND;
    float* out = (float*)d_out;

    cudaFuncSetAttribute(fused_edge_sender, cudaFuncAttributeMaxDynamicSharedMemorySize, SMEM_BYTES);
    cudaFuncSetAttribute(fused_node,        cudaFuncAttributeMaxDynamicSharedMemorySize, SMEM_BYTES);

    detect_kernel<<<1, 1>>>((const int*)eidx);
    zero_kernel<<<(N * ND + 255) / 256, 256>>>(N);
    prep_kernel<0><<<512, 256>>>(ew1, ew2, 384);
    prep_kernel<1><<<512, 256>>>(nw1, nw2, 256);
    prep_kernel<2><<<512, 256>>>(sw1, sw2, 128);

    int nEdgeBlk = (E + TILE - 1) / TILE;
    int nNodeBlk = (N + TILE - 1) / TILE;

    // edge (writes edge_out region 2 + scatter) and sender (region 0), one launch
    fused_edge_sender<<<nEdgeBlk + nNodeBlk, 256, SMEM_BYTES>>>(
        sender_x, eidx, receiver_x, edge_attr,
        eb1, eb2, eg, ebeta,
        sb1, sb2, sg, sbeta,
        out + 2LL * N * ND, out, E, N, nEdgeBlk);

    // node: reads g_agg/g_cnt, writes receiver_out (region 1)
    fused_node<<<nNodeBlk, 256, SMEM_BYTES>>>(
        receiver_x, nb1, nb2, ng, nbeta,
        out + (long long)N * ND, N);
}

// round 10
// speedup vs baseline: 8.4806x; 1.2815x over previous
#include <cuda_runtime.h>
#include <cuda_fp16.h>
#include <cstdint>
#include <math.h>

#define ND 128
#define NMAX 40000
#define LN_EPS 1e-5f
#define TILE 128

// ---------------- device scratch (allocation-free) ----------------
__device__ float g_agg[(long long)NMAX * ND];
__device__ float g_cnt[NMAX];
__device__ int   g_is64;
// weights pre-converted to fp16 AND pre-packed into m16n8k16 B-fragment chunk layout:
// g_w1p[mode]: per k-chunk c (32 k): 4096 u32 = ((kb*32+nt)*32+lane)*2+r, each u32 = half2(k0,k0+1)
// g_w2p[mode]: per k-chunk c:        2048 u32 = ((kb*16+nt)*32+lane)*2+r
__device__ uint32_t g_w1p[3][12 * 4096];
__device__ uint32_t g_w2p[3][8 * 2048];

// ---------------- helpers ----------------
__device__ __forceinline__ uint32_t pack_h2(float x, float y) {
    __half2 h = __floats2half2_rn(x, y);
    return *(uint32_t*)&h;
}
__device__ __forceinline__ uint32_t smem_u32(const void* p) {
    uint32_t a;
    asm("{ .reg .u64 t; cvta.to.shared.u64 t, %1; cvt.u32.u64 %0, t; }" : "=r"(a) : "l"(p));
    return a;
}
__device__ __forceinline__ void red_add_v4(float* p, float4 v) {
    asm volatile("red.global.add.v4.f32 [%0], {%1,%2,%3,%4};"
                 :: "l"(p), "f"(v.x), "f"(v.y), "f"(v.z), "f"(v.w) : "memory");
}
// m16n8k16 fp16 mma: A row-major (4 half2 regs), B col-major (2 half2 regs), C/D f32
__device__ __forceinline__ void mma16(float d[4], const uint32_t a[4], const uint32_t b[2]) {
    asm volatile("mma.sync.aligned.m16n8k16.row.col.f32.f16.f16.f32 "
        "{%0,%1,%2,%3}, {%4,%5,%6,%7}, {%8,%9}, {%0,%1,%2,%3};"
        : "+f"(d[0]), "+f"(d[1]), "+f"(d[2]), "+f"(d[3])
        : "r"(a[0]), "r"(a[1]), "r"(a[2]), "r"(a[3]), "r"(b[0]), "r"(b[1]));
}
__device__ __forceinline__ void cpa16(uint32_t dst, const void* src) {
    asm volatile("cp.async.cg.shared.global [%0], [%1], 16;" :: "r"(dst), "l"(src) : "memory");
}
#define CP_COMMIT() asm volatile("cp.async.commit_group;" ::: "memory")
#define CP_WAIT0()  asm volatile("cp.async.wait_group 0;" ::: "memory")
#define CP_WAIT1()  asm volatile("cp.async.wait_group 1;" ::: "memory")

// ---------------- small kernels ----------------
__global__ void detect_kernel(const int* __restrict__ p) {
    int all0 = 1;
    for (int i = 1; i < 200; i += 2)
        if (p[i] != 0) all0 = 0;
    g_is64 = all0;
}
__global__ void zero_kernel(int n) {
    long long i = (long long)blockIdx.x * blockDim.x + threadIdx.x;
    long long tot = (long long)n * ND;
    if (i < tot) g_agg[i] = 0.f;
    if (i < n)   g_cnt[i] = 0.f;
}
// convert + pack weights into fp16 fragment-chunk layout
template<int S>
__global__ void prep_kernel(const float* __restrict__ w1, const float* __restrict__ w2, int K1) {
    int nc1 = K1 / 32;
    int tot1 = nc1 * 4096;
    for (int i = blockIdx.x * blockDim.x + threadIdx.x; i < tot1; i += gridDim.x * blockDim.x) {
        int c = i >> 12, rem = i & 4095;
        int r = rem & 1, lane = (rem >> 1) & 31, nt = (rem >> 6) & 31, kb = rem >> 11;
        int n = nt * 8 + (lane >> 2);
        int k0 = c * 32 + kb * 16 + (lane & 3) * 2 + r * 8;
        g_w1p[S][i] = pack_h2(w1[k0 * 256 + n], w1[(k0 + 1) * 256 + n]);
    }
    int tot2 = 8 * 2048;
    for (int i = blockIdx.x * blockDim.x + threadIdx.x; i < tot2; i += gridDim.x * blockDim.x) {
        int c = i >> 11, rem = i & 2047;
        int r = rem & 1, lane = (rem >> 1) & 31, nt = (rem >> 6) & 15, kb = rem >> 10;
        int n = nt * 8 + (lane >> 2);
        int k0 = c * 32 + kb * 16 + (lane & 3) * 2 + r * 8;
        g_w2p[S][i] = pack_h2(w2[k0 * 128 + n], w2[(k0 + 1) * 128 + n]);
    }
}

// ---------------- smem layout (float units) ----------------
//   [0..128) idxs [128..256) idxd [256..384) rcp [384..512) smean [512..640) sinv
//   [640..4736)   bpack2: 2 x 2048 u32 (GEMM2 W chunks)
//   [4736..22144) region R:
//     hpack: 16384 u32 (GEMM2 A, half2)     @4736
//     lnbuf: 128x132 fp32 overlay           @4736
//     GEMM1 overlay: xraw 2 x 4608 fp32 @4736 ; bpack1 2 x 4096 u32 @13952
#define SMEM_FLOATS 22144
#define SMEM_BYTES  (SMEM_FLOATS * 4)   // 88576

// MODE 0: edge (K1=384, gather + scatter), MODE 1: node (K1=256), MODE 2: sender (K1=128)
template<int MODE>
__device__ __forceinline__ void mlp_body(
    int bid, float* sm, uint32_t sbase,
    const float* __restrict__ xa, const void* __restrict__ eidx,
    const float* __restrict__ xb, const float* __restrict__ xc,
    const float* __restrict__ b1, const float* __restrict__ b2,
    const float* __restrict__ gamma, const float* __restrict__ beta,
    const float* __restrict__ resid, float* __restrict__ outp,
    int nrows, int nedges)
{
    constexpr int K1  = (MODE == 0) ? 384 : (MODE == 1 ? 256 : 128);
    constexpr int NC1 = K1 / 32;
    int*   idxs  = (int*)sm;
    int*   idxd  = (int*)(sm + 128);
    float* rcp   = sm + 256;
    float* smean = sm + 384;
    float* sinv  = sm + 512;
    uint32_t* bpack2 = (uint32_t*)(sm + 640);
    uint32_t* hpack  = (uint32_t*)(sm + 4736);
    float* lnbuf  = sm + 4736;
    float* xraw   = sm + 4736;
    uint32_t* bpack1 = (uint32_t*)(sm + 13952);
    const uint32_t xr_b  = sbase + 4736u * 4u;
    const uint32_t bp1_b = sbase + 13952u * 4u;
    const uint32_t bp2_b = sbase + 640u * 4u;

    const int tid  = threadIdx.x;
    const int lane = tid & 31;
    const int wid  = tid >> 5;
    const int wm   = wid & 1;        // warp m-block (rows wm*64..)
    const int wn   = wid >> 1;       // warp n-block
    const long long row0 = (long long)bid * TILE;

    // -------- per-tile metadata --------
    if (MODE == 0) {
        if (tid < TILE) {
            int is64 = g_is64;
            long long e = row0 + tid; if (e >= nrows) e = nrows - 1;
            if (is64) {
                const long long* p = (const long long*)eidx;
                idxs[tid] = (int)p[e];
                idxd[tid] = (int)p[(long long)nedges + e];
            } else {
                const int* p = (const int*)eidx;
                idxs[tid] = p[e];
                idxd[tid] = p[nedges + e];
            }
        }
    } else if (MODE == 1) {
        if (tid < TILE) {
            long long r = row0 + tid;
            float c = (r < nrows) ? g_cnt[r] : 1.f;
            rcp[tid] = 1.f / fmaxf(c, 1.f);
        }
    }
    __syncthreads();

    const uint32_t* w1p = g_w1p[MODE];
    const uint32_t* w2p = g_w2p[MODE];

    // issue one GEMM1 chunk (X raw rows + W1 fragment-pack), one commit group
    auto issue1 = [&](int c) {
        int buf = c & 1;
        #pragma unroll
        for (int t = 0; t < 4; t++) {
            int seg = tid + t * 256;          // 0..1023 (128 rows x 8 16B-segs)
            int row = seg >> 3, f = seg & 7;
            long long grow = row0 + row; if (grow >= nrows) grow = nrows - 1;
            const float* src;
            if (MODE == 0) {
                src = (c < 4) ? xa + (long long)idxs[row] * ND + c * 32 + f * 4
                    : (c < 8) ? xb + (long long)idxd[row] * ND + (c - 4) * 32 + f * 4
                              : xc + grow * ND + (c - 8) * 32 + f * 4;
            } else if (MODE == 1) {
                src = (c < 4) ? xa + grow * ND + c * 32 + f * 4
                              : g_agg + grow * ND + (c - 4) * 32 + f * 4;
            } else {
                src = xa + grow * ND + c * 32 + f * 4;
            }
            cpa16(xr_b + (uint32_t)(buf * 4608 + row * 36 + f * 4) * 4u, src);
        }
        #pragma unroll
        for (int t = 0; t < 4; t++) {
            int seg = tid + t * 256;          // 0..1023 16B-segs (4096 u32)
            cpa16(bp1_b + (uint32_t)(buf * 4096 + seg * 4) * 4u,
                  w1p + (long long)c * 4096 + seg * 4);
        }
        CP_COMMIT();
    };

    issue1(0);
    issue1(1);

    // ================= GEMM1: D1[128,256] = X[128,K1] @ W1 =================
    float d1[4][8][4];
    #pragma unroll
    for (int i = 0; i < 4; i++)
        #pragma unroll
        for (int j = 0; j < 8; j++)
            #pragma unroll
            for (int c = 0; c < 4; c++) d1[i][j][c] = 0.f;

    for (int c = 0; c < NC1; c++) {
        if (c == NC1 - 1) { CP_WAIT0(); } else { CP_WAIT1(); }
        __syncthreads();
        const float* xb_ = xraw + (c & 1) * 4608;
        const uint32_t* wb_ = bpack1 + (c & 1) * 4096;
        float rc1[4], rc2[4];
        if (MODE == 1 && c >= 4) {
            #pragma unroll
            for (int i = 0; i < 4; i++) {
                int row = wm * 64 + i * 16 + (lane >> 2);
                rc1[i] = rcp[row]; rc2[i] = rcp[row + 8];
            }
        }
        #pragma unroll
        for (int kb = 0; kb < 2; kb++) {
            uint2 b[8];
            #pragma unroll
            for (int j = 0; j < 8; j++)
                b[j] = *(const uint2*)(wb_ + (((kb * 32 + wn * 8 + j) * 32 + lane) << 1));
            #pragma unroll
            for (int i = 0; i < 4; i++) {
                int row = wm * 64 + i * 16 + (lane >> 2);
                const float* ap = xb_ + row * 36 + kb * 16 + (lane & 3) * 2;
                float2 f0 = *(const float2*)ap;            // row g,   k lo
                float2 f1 = *(const float2*)(ap + 8);      // row g,   k hi
                const float* ap2 = ap + 288;               // +8 rows
                float2 f2 = *(const float2*)ap2;           // row g+8, k lo
                float2 f3 = *(const float2*)(ap2 + 8);     // row g+8, k hi
                if (MODE == 1 && c >= 4) {
                    f0.x *= rc1[i]; f0.y *= rc1[i]; f1.x *= rc1[i]; f1.y *= rc1[i];
                    f2.x *= rc2[i]; f2.y *= rc2[i]; f3.x *= rc2[i]; f3.y *= rc2[i];
                }
                uint32_t ar[4];
                ar[0] = pack_h2(f0.x, f0.y);
                ar[1] = pack_h2(f2.x, f2.y);
                ar[2] = pack_h2(f1.x, f1.y);
                ar[3] = pack_h2(f3.x, f3.y);
                #pragma unroll
                for (int j = 0; j < 8; j++)
                    mma16(d1[i][j], ar, (const uint32_t*)&b[j]);
            }
        }
        __syncthreads();
        if (c + 2 < NC1) issue1(c + 2);
    }

    // prefetch GEMM2 W chunks 0,1 (bpack2 disjoint from hpack)
    auto issue2 = [&](int c2) {
        int buf = c2 & 1;
        #pragma unroll
        for (int t = 0; t < 2; t++) {
            int seg = tid + t * 256;          // 0..511 16B-segs (2048 u32)
            cpa16(bp2_b + (uint32_t)(buf * 2048 + seg * 4) * 4u,
                  w2p + (long long)c2 * 2048 + seg * 4);
        }
        CP_COMMIT();
    };
    issue2(0);
    issue2(1);

    // ======== epilogue1: bias + SiLU -> hpack (half2, GEMM2 A-fragment layout) ========
    #pragma unroll
    for (int j = 0; j < 8; j++) {
        int nbase = wn * 64 + j * 8 + (lane & 3) * 2;
        float bv0 = b1[nbase], bv1 = b1[nbase + 1];
        int kb2 = wn * 4 + (j >> 1);
        #pragma unroll
        for (int i = 0; i < 4; i++) {
            int mt = wm * 4 + i;
            uint32_t* hp = hpack + (((kb2 * 8 + mt) * 32 + lane) << 2);
            uint2 st;
            {
                float v0 = d1[i][j][0] + bv0; v0 = v0 / (1.f + __expf(-v0));
                float v1 = d1[i][j][1] + bv1; v1 = v1 / (1.f + __expf(-v1));
                st.x = pack_h2(v0, v1);                       // row g
            }
            {
                float v0 = d1[i][j][2] + bv0; v0 = v0 / (1.f + __expf(-v0));
                float v1 = d1[i][j][3] + bv1; v1 = v1 / (1.f + __expf(-v1));
                st.y = pack_h2(v0, v1);                       // row g+8
            }
            *(uint2*)(hp + ((j & 1) << 1)) = st;              // regs r=2*(j&1)+{0,1}
        }
    }
    __syncthreads();

    // ================= GEMM2: D2[128,128] = H[128,256] @ W2 =================
    float d2[4][4][4];
    #pragma unroll
    for (int i = 0; i < 4; i++)
        #pragma unroll
        for (int j = 0; j < 4; j++)
            #pragma unroll
            for (int c = 0; c < 4; c++) d2[i][j][c] = 0.f;

    for (int c2 = 0; c2 < 8; c2++) {
        if (c2 == 7) { CP_WAIT0(); } else { CP_WAIT1(); }
        __syncthreads();
        const uint32_t* wb_ = bpack2 + (c2 & 1) * 2048;
        #pragma unroll
        for (int kb = 0; kb < 2; kb++) {
            int kb2 = c2 * 2 + kb;
            uint4 a[4]; uint2 b[4];
            #pragma unroll
            for (int i = 0; i < 4; i++)
                a[i] = *(const uint4*)(hpack + (((kb2 * 8 + wm * 4 + i) * 32 + lane) << 2));
            #pragma unroll
            for (int j = 0; j < 4; j++)
                b[j] = *(const uint2*)(wb_ + (((kb * 16 + wn * 4 + j) * 32 + lane) << 1));
            #pragma unroll
            for (int i = 0; i < 4; i++) {
                uint32_t ar[4] = {a[i].x, a[i].y, a[i].z, a[i].w};
                #pragma unroll
                for (int j = 0; j < 4; j++)
                    mma16(d2[i][j], ar, (const uint32_t*)&b[j]);
            }
        }
        __syncthreads();
        if (c2 + 2 < 8) issue2(c2 + 2);
    }

    // ======== epilogue2: bias -> lnbuf, LN stats, LN+residual+store+scatter ========
    #pragma unroll
    for (int j = 0; j < 4; j++) {
        int nbase = wn * 32 + j * 8 + (lane & 3) * 2;
        float bv0 = b2[nbase], bv1 = b2[nbase + 1];
        #pragma unroll
        for (int i = 0; i < 4; i++) {
            int mbase = wm * 64 + i * 16 + (lane >> 2);
            #pragma unroll
            for (int cc = 0; cc < 4; cc++) {
                int m = mbase + (cc >> 1) * 8;
                int n = nbase + (cc & 1);
                lnbuf[m * 132 + n] = d2[i][j][cc] + ((cc & 1) ? bv1 : bv0);
            }
        }
    }
    __syncthreads();
    {   // per-row mean/inv-std: 2 threads per row
        int row = tid >> 1, h = tid & 1;
        const float* p = lnbuf + row * 132 + h * 64;
        float s = 0.f, q = 0.f;
        #pragma unroll
        for (int k = 0; k < 64; k++) { float v = p[k]; s += v; q += v * v; }
        s += __shfl_xor_sync(0xffffffffu, s, 1);
        q += __shfl_xor_sync(0xffffffffu, q, 1);
        float mean = s * (1.f / 128.f);
        float var  = q * (1.f / 128.f) - mean * mean;
        smean[row] = mean;
        sinv[row]  = rsqrtf(var + LN_EPS);
    }
    __syncthreads();
    #pragma unroll
    for (int t = 0; t < 16; t++) {
        int idx = tid + t * 256;               // 0..4095: row(128) x f(32 float4)
        int r2 = idx >> 5, f = idx & 31;
        long long grow = row0 + r2;
        if (grow < nrows) {
            float4 vv = *(const float4*)(lnbuf + r2 * 132 + f * 4);
            float mean = smean[r2], inv = sinv[r2];
            float4 gm = ((const float4*)gamma)[f];
            float4 bt = ((const float4*)beta)[f];
            float4 ln;
            ln.x = (vv.x - mean) * inv * gm.x + bt.x;
            ln.y = (vv.y - mean) * inv * gm.y + bt.y;
            ln.z = (vv.z - mean) * inv * gm.z + bt.z;
            ln.w = (vv.w - mean) * inv * gm.w + bt.w;
            float4 rs = ((const float4*)(resid + grow * ND))[f];
            float4 o = make_float4(ln.x + rs.x, ln.y + rs.y, ln.z + rs.z, ln.w + rs.w);
            ((float4*)(outp + grow * ND))[f] = o;
            if (MODE == 0)
                red_add_v4(g_agg + (long long)idxd[r2] * ND + f * 4, ln);
        }
    }
    if (MODE == 0 && tid < TILE) {
        long long grow = row0 + tid;
        if (grow < nrows) atomicAdd(&g_cnt[idxd[tid]], 1.f);
    }
}

// ---------------- kernels ----------------
__global__ void __launch_bounds__(256, 1)
fused_edge_sender(const float* __restrict__ sender_x, const void* __restrict__ eidx,
                  const float* __restrict__ receiver_x, const float* __restrict__ edge_attr,
                  const float* __restrict__ eb1, const float* __restrict__ eb2,
                  const float* __restrict__ eg, const float* __restrict__ ebeta,
                  const float* __restrict__ sb1, const float* __restrict__ sb2,
                  const float* __restrict__ sg, const float* __restrict__ sbeta,
                  float* edge_out, float* sender_out, int E, int N, int nEdgeBlk)
{
    extern __shared__ float sm[];
    uint32_t sbase = smem_u32(sm);
    if ((int)blockIdx.x < nEdgeBlk)
        mlp_body<0>(blockIdx.x, sm, sbase, sender_x, eidx, receiver_x, edge_attr,
                    eb1, eb2, eg, ebeta, edge_attr, edge_out, E, E);
    else
        mlp_body<2>(blockIdx.x - nEdgeBlk, sm, sbase, sender_x, nullptr, nullptr, nullptr,
                    sb1, sb2, sg, sbeta, sender_x, sender_out, N, 0);
}

__global__ void __launch_bounds__(256, 1)
fused_node(const float* __restrict__ receiver_x,
           const float* __restrict__ nb1, const float* __restrict__ nb2,
           const float* __restrict__ ng, const float* __restrict__ nbeta,
           float* recv_out, int N)
{
    extern __shared__ float sm[];
    uint32_t sbase = smem_u32(sm);
    mlp_body<1>(blockIdx.x, sm, sbase, receiver_x, nullptr, nullptr, nullptr,
                nb1, nb2, ng, nbeta, receiver_x, recv_out, N, 0);
}

// ---------------- host launch ----------------
extern "C" void kernel_launch(void* const* d_in, const int* in_sizes, int n_in,
                              void* d_out, int out_size)
{
    const float* sender_x   = (const float*)d_in[0];
    const float* receiver_x = (const float*)d_in[1];
    const float* edge_attr  = (const float*)d_in[2];
    const void*  eidx       = d_in[3];
    const float* ew1 = (const float*)d_in[4],  *eb1   = (const float*)d_in[5];
    const float* ew2 = (const float*)d_in[6],  *eb2   = (const float*)d_in[7];
    const float* eg  = (const float*)d_in[8],  *ebeta = (const float*)d_in[9];
    const float* nw1 = (const float*)d_in[10], *nb1   = (const float*)d_in[11];
    const float* nw2 = (const float*)d_in[12], *nb2   = (const float*)d_in[13];
    const float* ng  = (const float*)d_in[14], *nbeta = (const float*)d_in[15];
    const float* sw1 = (const float*)d_in[16], *sb1   = (const float*)d_in[17];
    const float* sw2 = (const float*)d_in[18], *sb2   = (const float*)d_in[19];
    const float* sg  = (const float*)d_in[20], *sbeta = (const float*)d_in[21];

    int N = in_sizes[0] / ND;
    int E = in_sizes[2] / ND;
    float* out = (float*)d_out;

    cudaFuncSetAttribute(fused_edge_sender, cudaFuncAttributeMaxDynamicSharedMemorySize, SMEM_BYTES);
    cudaFuncSetAttribute(fused_node,        cudaFuncAttributeMaxDynamicSharedMemorySize, SMEM_BYTES);

    detect_kernel<<<1, 1>>>((const int*)eidx);
    zero_kernel<<<(N * ND + 255) / 256, 256>>>(N);
    prep_kernel<0><<<512, 256>>>(ew1, ew2, 384);
    prep_kernel<1><<<512, 256>>>(nw1, nw2, 256);
    prep_kernel<2><<<512, 256>>>(sw1, sw2, 128);

    int nEdgeBlk = (E + TILE - 1) / TILE;
    int nNodeBlk = (N + TILE - 1) / TILE;

    // edge (writes edge_out region 2 + scatter) and sender (region 0), one launch
    fused_edge_sender<<<nEdgeBlk + nNodeBlk, 256, SMEM_BYTES>>>(
        sender_x, eidx, receiver_x, edge_attr,
        eb1, eb2, eg, ebeta,
        sb1, sb2, sg, sbeta,
        out + 2LL * N * ND, out, E, N, nEdgeBlk);

    // node: reads g_agg/g_cnt, writes receiver_out (region 1)
    fused_node<<<nNodeBlk, 256, SMEM_BYTES>>>(
        receiver_x, nb1, nb2, ng, nbeta,
        out + (long long)N * ND, N);
}